// round 3
// baseline (speedup 1.0000x reference)
#include <cuda_runtime.h>
#include <math.h>

// Problem dims
#define BB   32
#define LL   512
#define EE   768
#define HH   1024
#define OO   128
#define BL   (BB * LL)          // 16384

// ---------------------------------------------------------------------------
// Static scratch (allocation-free): xp buffer reused across layers, r1, r2
// ---------------------------------------------------------------------------
__device__ float g_xp[(size_t)BL * HH];
__device__ float g_r1[(size_t)BL * HH];
__device__ float g_r2[(size_t)BL * HH];

// grid-barrier state (monotonic generation; deterministic across replays:
// g_cnt always returns to 0, comparisons on g_gen are relative to a base
// read at kernel start)
__device__ unsigned g_cnt = 0;
__device__ unsigned g_gen = 0;

#define SEL_EXT 0
#define SEL_R1  1
#define SEL_R2  2
#define SEL_XP  3

__device__ __forceinline__ const float* pick_src(int sel, const float* ext) {
    if (sel == SEL_R1) return g_r1;
    if (sel == SEL_R2) return g_r2;
    if (sel == SEL_XP) return g_xp;
    return ext;
}
__device__ __forceinline__ float* pick_dst(int sel, float* ext) {
    if (sel == SEL_XP) return g_xp;
    if (sel == SEL_R1) return g_r1;
    if (sel == SEL_R2) return g_r2;
    return ext;
}

// ---------------------------------------------------------------------------
// SGEMM: C[M,N] = A[M,K] * W[N,K]^T + bias1[n] (+ bias2[n])
// 128x128 block tile, BK=8, 256 threads, 8x8 per thread.
// ---------------------------------------------------------------------------
#define BM 128
#define BN 128
#define BK 8

__global__ __launch_bounds__(256) void sgemm_bias(
    const float* __restrict__ Aext, int Asel,
    const float* __restrict__ W,
    float* __restrict__ Cext, int Csel,
    const float* __restrict__ bias1, const float* __restrict__ bias2,
    int M, int N, int K)
{
    const float* A = pick_src(Asel, Aext);
    float* C = pick_dst(Csel, Cext);

    __shared__ float As[BK][BM];
    __shared__ float Bs[BK][BN];

    const int tid = threadIdx.x;
    const int tx = tid & 15;
    const int ty = tid >> 4;
    const int m0 = blockIdx.y * BM;
    const int n0 = blockIdx.x * BN;

    const int la_r = tid >> 1;        // 0..127
    const int la_k = (tid & 1) * 4;   // 0 or 4

    float acc[8][8];
    #pragma unroll
    for (int i = 0; i < 8; i++)
        #pragma unroll
        for (int j = 0; j < 8; j++) acc[i][j] = 0.0f;

    for (int k0 = 0; k0 < K; k0 += BK) {
        float4 av = *(const float4*)(A + (size_t)(m0 + la_r) * K + k0 + la_k);
        float4 bv = *(const float4*)(W + (size_t)(n0 + la_r) * K + k0 + la_k);
        __syncthreads();
        As[la_k + 0][la_r] = av.x; As[la_k + 1][la_r] = av.y;
        As[la_k + 2][la_r] = av.z; As[la_k + 3][la_r] = av.w;
        Bs[la_k + 0][la_r] = bv.x; Bs[la_k + 1][la_r] = bv.y;
        Bs[la_k + 2][la_r] = bv.z; Bs[la_k + 3][la_r] = bv.w;
        __syncthreads();
        #pragma unroll
        for (int kk = 0; kk < BK; kk++) {
            float a[8], b[8];
            *(float4*)(a)     = *(const float4*)&As[kk][ty * 4];
            *(float4*)(a + 4) = *(const float4*)&As[kk][ty * 4 + 64];
            *(float4*)(b)     = *(const float4*)&Bs[kk][tx * 4];
            *(float4*)(b + 4) = *(const float4*)&Bs[kk][tx * 4 + 64];
            #pragma unroll
            for (int i = 0; i < 8; i++)
                #pragma unroll
                for (int j = 0; j < 8; j++)
                    acc[i][j] += a[i] * b[j];
        }
    }

    #pragma unroll
    for (int jg = 0; jg < 2; jg++) {
        const int n = n0 + tx * 4 + jg * 64;
        float4 bb = make_float4(0.f, 0.f, 0.f, 0.f);
        if (bias1) {
            float4 t = *(const float4*)(bias1 + n);
            bb.x += t.x; bb.y += t.y; bb.z += t.z; bb.w += t.w;
        }
        if (bias2) {
            float4 t = *(const float4*)(bias2 + n);
            bb.x += t.x; bb.y += t.y; bb.z += t.z; bb.w += t.w;
        }
        #pragma unroll
        for (int i = 0; i < 8; i++) {
            const int ml = (i < 4) ? (ty * 4 + i) : (64 + ty * 4 + i - 4);
            const int m  = m0 + ml;
            float4 v;
            v.x = acc[i][jg * 4 + 0] + bb.x;
            v.y = acc[i][jg * 4 + 1] + bb.y;
            v.z = acc[i][jg * 4 + 2] + bb.z;
            v.w = acc[i][jg * 4 + 3] + bb.w;
            *(float4*)(C + (size_t)m * N + n) = v;
        }
    }
}

// ---------------------------------------------------------------------------
// Persistent RNN layer: r[:,t,:] = tanh(xp[:,t,:] + r[:,t-1,:] @ W_hh^T),
// t = 0..511 (h_{-1}=0), one kernel, software grid barrier between steps.
//
// Grid: 128 blocks = 4 batch-groups (8 batches) x 32 col-groups (32 cols).
// Co-residency guaranteed: 128 blocks <= 148 SMs, 1 block/SM (166KB smem).
// Block: 512 threads = 16 warps. warp = (khalf<<3)|batch ; lane = col.
// Each thread computes a half-K partial dot; partials combined via smem.
// W slice (32 rows x 1024, padded stride 1028 -> conflict-free LDS.128)
// is staged in smem ONCE for the whole layer.
// ---------------------------------------------------------------------------
#define WPAD 1028
#define RNN_BLOCKS 128
#define RNN_SMEM_FLOATS (32 * WPAD + 8 * WPAD + 512)

__global__ __launch_bounds__(512) void rnn_layer_kernel(
    int rsel, const float* __restrict__ W)
{
    float* r = (rsel == SEL_R1) ? g_r1 : g_r2;

    extern __shared__ float sm[];
    float* Wsm = sm;                       // 32 x WPAD
    float* hsm = sm + 32 * WPAD;           // 8 x WPAD
    float* psm = sm + 40 * WPAD;           // 512 partials

    const int tid  = threadIdx.x;
    const int warp = tid >> 5;
    const int lane = tid & 31;
    const int bg = blockIdx.x >> 5;        // 0..3
    const int cg = blockIdx.x & 31;        // 0..31
    const int b0 = bg * 8;
    const int c0 = cg * 32;
    const int kh = warp >> 3;              // k-half: 0/1
    const int bw = warp & 7;               // batch within group
    const int b  = b0 + bw;
    const int c  = c0 + lane;

    // stage W rows c0..c0+31 (full K) once: 8192 float4, 16 per thread
    #pragma unroll
    for (int i = tid; i < 8192; i += 512) {
        const int rr = i >> 8;
        const int q  = (i & 255) << 2;
        float4 v = *(const float4*)(W + (size_t)(c0 + rr) * HH + q);
        *(float4*)&Wsm[rr * WPAD + q] = v;
    }

    // barrier generation base (stable: no bump can occur before every block
    // has read it, since bumps require all arrivals and arrival follows read)
    __shared__ unsigned s_base;
    if (tid == 0) s_base = *(volatile unsigned*)&g_gen;
    __syncthreads();
    const unsigned base = s_base;

    const float4* wp = (const float4*)&Wsm[lane * WPAD + kh * 512];
    const float4* hp = (const float4*)&hsm[bw  * WPAD + kh * 512];

    for (int t = 0; t < LL; t++) {
        if (t > 0) {
            // stage h rows b0..b0+7 from r[:, t-1, :]: 2048 float4, 4/thread
            #pragma unroll
            for (int i = tid; i < 2048; i += 512) {
                const int rr = i >> 8;
                const int q  = (i & 255) << 2;
                float4 v = *(const float4*)(r + ((size_t)(b0 + rr) * LL + (t - 1)) * HH + q);
                *(float4*)&hsm[rr * WPAD + q] = v;
            }
            __syncthreads();

            float4 acc = make_float4(0.f, 0.f, 0.f, 0.f);
            #pragma unroll 8
            for (int q = 0; q < 128; q++) {
                const float4 w = wp[q];
                const float4 h = hp[q];    // broadcast across warp
                acc.x += w.x * h.x;
                acc.y += w.y * h.y;
                acc.z += w.z * h.z;
                acc.w += w.w * h.w;
            }
            psm[warp * 32 + lane] = (acc.x + acc.y) + (acc.z + acc.w);
            __syncthreads();
        }

        if (warp < 8) {
            const float dot = (t > 0)
                ? psm[warp * 32 + lane] + psm[(warp + 8) * 32 + lane]
                : 0.0f;
            const size_t off = ((size_t)b * LL + t) * HH + c;
            r[off] = tanhf(g_xp[off] + dot);
        }

        // ---- grid barrier (release h_t to all blocks) ----
        __threadfence();
        __syncthreads();
        if (tid == 0) {
            const unsigned arrived = atomicAdd(&g_cnt, 1);
            if (arrived == RNN_BLOCKS - 1) {
                g_cnt = 0;
                __threadfence();
                atomicAdd(&g_gen, 1);
            } else {
                const unsigned target = base + (unsigned)t + 1;
                while ((int)(*(volatile unsigned*)&g_gen - target) < 0) { }
            }
        }
        __syncthreads();
    }
}

// ---------------------------------------------------------------------------
// Launch: 6 graph nodes total
// ---------------------------------------------------------------------------
extern "C" void kernel_launch(void* const* d_in, const int* in_sizes, int n_in,
                              void* d_out, int out_size)
{
    const float* x     = (const float*)d_in[0];
    const float* W_ih1 = (const float*)d_in[1];
    const float* W_hh1 = (const float*)d_in[2];
    const float* b_ih1 = (const float*)d_in[3];
    const float* b_hh1 = (const float*)d_in[4];
    const float* W_ih2 = (const float*)d_in[5];
    const float* W_hh2 = (const float*)d_in[6];
    const float* b_ih2 = (const float*)d_in[7];
    const float* b_hh2 = (const float*)d_in[8];
    const float* W1    = (const float*)d_in[9];
    const float* b1    = (const float*)d_in[10];
    const float* W2    = (const float*)d_in[11];
    const float* b2    = (const float*)d_in[12];
    float* out = (float*)d_out;

    static int smem_set = 0;
    if (!smem_set) {
        cudaFuncSetAttribute(rnn_layer_kernel,
                             cudaFuncAttributeMaxDynamicSharedMemorySize,
                             RNN_SMEM_FLOATS * sizeof(float));
        smem_set = 1;
    }
    const size_t rnn_smem = RNN_SMEM_FLOATS * sizeof(float);

    const dim3 gBig(HH / BN, BL / BM);   // (8, 128)
    const dim3 gOut(OO / BN, BL / BM);   // (1, 128)

    // xp = x @ W_ih1^T + b_ih1 + b_hh1
    sgemm_bias<<<gBig, 256>>>(x, SEL_EXT, W_ih1, nullptr, SEL_XP,
                              b_ih1, b_hh1, BL, HH, EE);
    // layer 1 recurrence (persistent)
    rnn_layer_kernel<<<RNN_BLOCKS, 512, rnn_smem>>>(SEL_R1, W_hh1);

    // xp = r1 @ W_ih2^T + b_ih2 + b_hh2
    sgemm_bias<<<gBig, 256>>>(nullptr, SEL_R1, W_ih2, nullptr, SEL_XP,
                              b_ih2, b_hh2, BL, HH, HH);
    // layer 2 recurrence (persistent)
    rnn_layer_kernel<<<RNN_BLOCKS, 512, rnn_smem>>>(SEL_R2, W_hh2);

    // y = r1 @ W1^T + b1 ; z = r2 @ W2^T + b2
    sgemm_bias<<<gOut, 256>>>(nullptr, SEL_R1, W1, out, SEL_EXT,
                              b1, nullptr, BL, OO, HH);
    sgemm_bias<<<gOut, 256>>>(nullptr, SEL_R2, W2, out + (size_t)BL * OO, SEL_EXT,
                              b2, nullptr, BL, OO, HH);
}

// round 4
// speedup vs baseline: 1.6227x; 1.6227x over previous
#include <cuda_runtime.h>
#include <math.h>

// Problem dims
#define BB   32
#define LL   512
#define EE   768
#define HH   1024
#define OO   128
#define BL   (BB * LL)          // 16384

// ---------------------------------------------------------------------------
// Static scratch (allocation-free)
// ---------------------------------------------------------------------------
__device__ float g_xp[(size_t)BL * HH];
__device__ float g_r1[(size_t)BL * HH];
__device__ float g_r2[(size_t)BL * HH];

// per-batch-group barrier counters (monotonic within a layer; reset by init)
__device__ unsigned g_cnt4[4];

#define SEL_EXT 0
#define SEL_R1  1
#define SEL_R2  2
#define SEL_XP  3

__device__ __forceinline__ const float* pick_src(int sel, const float* ext) {
    if (sel == SEL_R1) return g_r1;
    if (sel == SEL_R2) return g_r2;
    if (sel == SEL_XP) return g_xp;
    return ext;
}
__device__ __forceinline__ float* pick_dst(int sel, float* ext) {
    if (sel == SEL_XP) return g_xp;
    if (sel == SEL_R1) return g_r1;
    if (sel == SEL_R2) return g_r2;
    return ext;
}

// packed f32x2 fma: acc = a*b + acc (two fp32 MACs per instruction)
__device__ __forceinline__ void fma2(unsigned long long& acc,
                                     unsigned long long a,
                                     unsigned long long b) {
    asm("fma.rn.f32x2 %0, %1, %2, %0;" : "+l"(acc) : "l"(a), "l"(b));
}
__device__ __forceinline__ float lo32(unsigned long long v) {
    return __uint_as_float((unsigned)v);
}
__device__ __forceinline__ float hi32(unsigned long long v) {
    return __uint_as_float((unsigned)(v >> 32));
}

// ---------------------------------------------------------------------------
// SGEMM: C[M,N] = A[M,K] * W[N,K]^T + bias1[n] (+ bias2[n])
// 128x128 tile, BK=8, 256 threads, 8x8 per thread, f32x2 packed FMA.
// ---------------------------------------------------------------------------
#define BM 128
#define BN 128
#define BK 8

__global__ __launch_bounds__(256) void sgemm_bias(
    const float* __restrict__ Aext, int Asel,
    const float* __restrict__ W,
    float* __restrict__ Cext, int Csel,
    const float* __restrict__ bias1, const float* __restrict__ bias2,
    int M, int N, int K)
{
    const float* A = pick_src(Asel, Aext);
    float* C = pick_dst(Csel, Cext);

    __shared__ float As[BK][BM];
    __shared__ float Bs[BK][BN];

    const int tid = threadIdx.x;
    const int tx = tid & 15;
    const int ty = tid >> 4;
    const int m0 = blockIdx.y * BM;
    const int n0 = blockIdx.x * BN;

    const int la_r = tid >> 1;        // 0..127
    const int la_k = (tid & 1) * 4;   // 0 or 4

    // acc[i][jp]: i = row (8), jp = col-pair (4) -> 8 cols
    unsigned long long acc[8][4];
    #pragma unroll
    for (int i = 0; i < 8; i++)
        #pragma unroll
        for (int j = 0; j < 4; j++) acc[i][j] = 0ull;

    for (int k0 = 0; k0 < K; k0 += BK) {
        float4 av = *(const float4*)(A + (size_t)(m0 + la_r) * K + k0 + la_k);
        float4 bv = *(const float4*)(W + (size_t)(n0 + la_r) * K + k0 + la_k);
        __syncthreads();
        As[la_k + 0][la_r] = av.x; As[la_k + 1][la_r] = av.y;
        As[la_k + 2][la_r] = av.z; As[la_k + 3][la_r] = av.w;
        Bs[la_k + 0][la_r] = bv.x; Bs[la_k + 1][la_r] = bv.y;
        Bs[la_k + 2][la_r] = bv.z; Bs[la_k + 3][la_r] = bv.w;
        __syncthreads();
        #pragma unroll
        for (int kk = 0; kk < BK; kk++) {
            float a[8];
            *(float4*)(a)     = *(const float4*)&As[kk][ty * 4];
            *(float4*)(a + 4) = *(const float4*)&As[kk][ty * 4 + 64];
            ulonglong2 bv0 = *(const ulonglong2*)&Bs[kk][tx * 4];
            ulonglong2 bv1 = *(const ulonglong2*)&Bs[kk][tx * 4 + 64];
            unsigned long long bp[4] = {bv0.x, bv0.y, bv1.x, bv1.y};
            #pragma unroll
            for (int i = 0; i < 8; i++) {
                unsigned long long ap;
                unsigned ai = __float_as_uint(a[i]);
                asm("mov.b64 %0, {%1, %1};" : "=l"(ap) : "r"(ai));
                #pragma unroll
                for (int jp = 0; jp < 4; jp++)
                    fma2(acc[i][jp], ap, bp[jp]);
            }
        }
    }

    #pragma unroll
    for (int jg = 0; jg < 2; jg++) {
        const int n = n0 + tx * 4 + jg * 64;
        float4 bb = make_float4(0.f, 0.f, 0.f, 0.f);
        if (bias1) {
            float4 t = *(const float4*)(bias1 + n);
            bb.x += t.x; bb.y += t.y; bb.z += t.z; bb.w += t.w;
        }
        if (bias2) {
            float4 t = *(const float4*)(bias2 + n);
            bb.x += t.x; bb.y += t.y; bb.z += t.z; bb.w += t.w;
        }
        #pragma unroll
        for (int i = 0; i < 8; i++) {
            const int ml = (i < 4) ? (ty * 4 + i) : (64 + ty * 4 + i - 4);
            const int m  = m0 + ml;
            unsigned long long p0 = acc[i][jg * 2 + 0];
            unsigned long long p1 = acc[i][jg * 2 + 1];
            float4 v;
            v.x = lo32(p0) + bb.x;
            v.y = hi32(p0) + bb.y;
            v.z = lo32(p1) + bb.z;
            v.w = hi32(p1) + bb.w;
            *(float4*)(C + (size_t)m * N + n) = v;
        }
    }
}

// ---------------------------------------------------------------------------
// Persistent RNN layer: r[:,t,:] = tanh(xp[:,t,:] + r[:,t-1,:] @ W_hh^T)
//
// Grid: 128 blocks = 4 batch-groups (8 batches) x 32 col-groups (32 cols).
// 1 block/SM (181KB smem), all co-resident.
// Block: 512 threads = 16 warps. warp <-> k-chunk (64 k), lane <-> col.
// Each thread: 8 batch accumulators (f32x2 packed pairs along k) — each W
// value loaded from smem ONCE and reused across 8 batches.
// Cross-warp k-reduction via psm; per-batch-group monotonic counter barrier.
// ---------------------------------------------------------------------------
#define WPAD 1028                      // floats; 1028 % 32 == 4 -> LDS.128 conflict-free
#define RNN_BLOCKS 128
#define RNN_SMEM_FLOATS (32 * WPAD + 8 * WPAD + 16 * 8 * 32)

__global__ __launch_bounds__(512) void rnn_layer_kernel(
    int rsel, const float* __restrict__ W)
{
    float* r = (rsel == SEL_R1) ? g_r1 : g_r2;

    extern __shared__ float sm[];
    float* Wsm = sm;                       // 32 x WPAD  (col-major rows = output cols)
    float* hsm = sm + 32 * WPAD;           // 8 x WPAD
    float* psm = sm + 40 * WPAD;           // 16 x 8 x 32 partials

    const int tid  = threadIdx.x;
    const int warp = tid >> 5;             // k-chunk 0..15
    const int lane = tid & 31;             // col within group
    const int bg = blockIdx.x >> 5;        // 0..3
    const int cg = blockIdx.x & 31;        // 0..31
    const int b0 = bg * 8;
    const int c0 = cg * 32;

    // stage W rows c0..c0+31 (full K) once: 8192 float4, 16 per thread
    #pragma unroll
    for (int i = tid; i < 8192; i += 512) {
        const int rr = i >> 8;
        const int q  = (i & 255) << 2;
        *(float4*)&Wsm[rr * WPAD + q] =
            *(const float4*)(W + (size_t)(c0 + rr) * HH + q);
    }

    const ulonglong2* wp  = (const ulonglong2*)&Wsm[lane * WPAD + warp * 64];
    const ulonglong2* hp0 = (const ulonglong2*)&hsm[warp * 64];
    // hsm row stride in ulonglong2 units: WPAD/4 = 257

    for (int t = 0; t < LL; t++) {
        if (t > 0) {
            // stage h rows b0..b0+7 from r[:, t-1, :]: 2048 float4, 4/thread
            #pragma unroll
            for (int i = tid; i < 2048; i += 512) {
                const int rr = i >> 8;
                const int q  = (i & 255) << 2;
                *(float4*)&hsm[rr * WPAD + q] =
                    *(const float4*)(r + ((size_t)(b0 + rr) * LL + (t - 1)) * HH + q);
            }
            __syncthreads();

            unsigned long long acc[8];
            #pragma unroll
            for (int b = 0; b < 8; b++) acc[b] = 0ull;

            #pragma unroll
            for (int q = 0; q < 16; q++) {
                const ulonglong2 wv = wp[q];
                #pragma unroll
                for (int b = 0; b < 8; b++) {
                    const ulonglong2 hv = hp0[b * 257 + q];  // broadcast
                    fma2(acc[b], wv.x, hv.x);
                    fma2(acc[b], wv.y, hv.y);
                }
            }

            #pragma unroll
            for (int b = 0; b < 8; b++)
                psm[warp * 256 + b * 32 + lane] = lo32(acc[b]) + hi32(acc[b]);
            __syncthreads();
        }

        // reduction + activation: warp = batch (0..7), lane = col
        if (warp < 8) {
            float dot = 0.0f;
            if (t > 0) {
                #pragma unroll
                for (int w = 0; w < 16; w++)
                    dot += psm[w * 256 + warp * 32 + lane];
            }
            const size_t off = ((size_t)(b0 + warp) * LL + t) * HH + (c0 + lane);
            r[off] = tanhf(g_xp[off] + dot);
        }

        // ---- per-batch-group barrier (release h_t to the 32 peer blocks) ----
        if (t < LL - 1) {
            __threadfence();
            __syncthreads();
            if (tid == 0) {
                atomicAdd(&g_cnt4[bg], 1u);
                const unsigned target = 32u * (unsigned)(t + 1);
                while (*(volatile unsigned*)&g_cnt4[bg] < target) { }
            }
            __syncthreads();
        }
    }
}

// reset barrier counters (run before each rnn layer -> deterministic replays)
__global__ void rnn_init_kernel()
{
    if (threadIdx.x < 4) g_cnt4[threadIdx.x] = 0u;
}

// ---------------------------------------------------------------------------
// Launch: 8 graph nodes
// ---------------------------------------------------------------------------
extern "C" void kernel_launch(void* const* d_in, const int* in_sizes, int n_in,
                              void* d_out, int out_size)
{
    const float* x     = (const float*)d_in[0];
    const float* W_ih1 = (const float*)d_in[1];
    const float* W_hh1 = (const float*)d_in[2];
    const float* b_ih1 = (const float*)d_in[3];
    const float* b_hh1 = (const float*)d_in[4];
    const float* W_ih2 = (const float*)d_in[5];
    const float* W_hh2 = (const float*)d_in[6];
    const float* b_ih2 = (const float*)d_in[7];
    const float* b_hh2 = (const float*)d_in[8];
    const float* W1    = (const float*)d_in[9];
    const float* b1    = (const float*)d_in[10];
    const float* W2    = (const float*)d_in[11];
    const float* b2    = (const float*)d_in[12];
    float* out = (float*)d_out;

    static int smem_set = 0;
    if (!smem_set) {
        cudaFuncSetAttribute(rnn_layer_kernel,
                             cudaFuncAttributeMaxDynamicSharedMemorySize,
                             RNN_SMEM_FLOATS * sizeof(float));
        smem_set = 1;
    }
    const size_t rnn_smem = RNN_SMEM_FLOATS * sizeof(float);

    const dim3 gBig(HH / BN, BL / BM);   // (8, 128)
    const dim3 gOut(OO / BN, BL / BM);   // (1, 128)

    // xp = x @ W_ih1^T + b_ih1 + b_hh1
    sgemm_bias<<<gBig, 256>>>(x, SEL_EXT, W_ih1, nullptr, SEL_XP,
                              b_ih1, b_hh1, BL, HH, EE);
    // layer 1 recurrence (persistent)
    rnn_init_kernel<<<1, 32>>>();
    rnn_layer_kernel<<<RNN_BLOCKS, 512, rnn_smem>>>(SEL_R1, W_hh1);

    // xp = r1 @ W_ih2^T + b_ih2 + b_hh2
    sgemm_bias<<<gBig, 256>>>(nullptr, SEL_R1, W_ih2, nullptr, SEL_XP,
                              b_ih2, b_hh2, BL, HH, HH);
    // layer 2 recurrence (persistent)
    rnn_init_kernel<<<1, 32>>>();
    rnn_layer_kernel<<<RNN_BLOCKS, 512, rnn_smem>>>(SEL_R2, W_hh2);

    // y = r1 @ W1^T + b1 ; z = r2 @ W2^T + b2
    sgemm_bias<<<gOut, 256>>>(nullptr, SEL_R1, W1, out, SEL_EXT,
                              b1, nullptr, BL, OO, HH);
    sgemm_bias<<<gOut, 256>>>(nullptr, SEL_R2, W2, out + (size_t)BL * OO, SEL_EXT,
                              b2, nullptr, BL, OO, HH);
}

// round 5
// speedup vs baseline: 1.8121x; 1.1168x over previous
#include <cuda_runtime.h>
#include <math.h>

// Problem dims
#define BB   32
#define LL   512
#define EE   768
#define HH   1024
#define OO   128
#define BL   (BB * LL)          // 16384

// ---------------------------------------------------------------------------
// Static scratch (allocation-free)
// ---------------------------------------------------------------------------
__device__ float g_xp[(size_t)BL * HH];
__device__ float g_r1[(size_t)BL * HH];
__device__ float g_r2[(size_t)BL * HH];

// per-batch-group barrier counters, padded to separate 128B lines
__device__ unsigned g_cnt4[4 * 32];

#define SEL_EXT 0
#define SEL_R1  1
#define SEL_R2  2
#define SEL_XP  3

__device__ __forceinline__ const float* pick_src(int sel, const float* ext) {
    if (sel == SEL_R1) return g_r1;
    if (sel == SEL_R2) return g_r2;
    if (sel == SEL_XP) return g_xp;
    return ext;
}
__device__ __forceinline__ float* pick_dst(int sel, float* ext) {
    if (sel == SEL_XP) return g_xp;
    if (sel == SEL_R1) return g_r1;
    if (sel == SEL_R2) return g_r2;
    return ext;
}

// packed f32x2 fma: acc = a*b + acc (two fp32 MACs per instruction)
__device__ __forceinline__ void fma2(unsigned long long& acc,
                                     unsigned long long a,
                                     unsigned long long b) {
    asm("fma.rn.f32x2 %0, %1, %2, %0;" : "+l"(acc) : "l"(a), "l"(b));
}
__device__ __forceinline__ float lo32(unsigned long long v) {
    return __uint_as_float((unsigned)v);
}
__device__ __forceinline__ float hi32(unsigned long long v) {
    return __uint_as_float((unsigned)(v >> 32));
}

// fast tanh via MUFU: tanh(x) = 1 - 2/(e^{2x}+1); clamp keeps fdividef exact-safe
__device__ __forceinline__ float fast_tanh(float x) {
    float xc = fminf(fmaxf(x, -15.0f), 15.0f);
    float e  = __expf(2.0f * xc);
    return 1.0f - __fdividef(2.0f, e + 1.0f);
}

// ---------------------------------------------------------------------------
// SGEMM: C[M,N] = A[M,K] * W[N,K]^T + bias1[n] (+ bias2[n])
// 128x128 tile, BK=8, 256 threads, 8x8/thread, f32x2 FMA,
// double-buffered smem (1 syncthreads per k-tile, LDG hidden under compute).
// ---------------------------------------------------------------------------
#define BM 128
#define BN 128
#define BK 8

__global__ __launch_bounds__(256) void sgemm_bias(
    const float* __restrict__ Aext, int Asel,
    const float* __restrict__ W,
    float* __restrict__ Cext, int Csel,
    const float* __restrict__ bias1, const float* __restrict__ bias2,
    int M, int N, int K)
{
    const float* A = pick_src(Asel, Aext);
    float* C = pick_dst(Csel, Cext);

    __shared__ float As[2][BK][BM];
    __shared__ float Bs[2][BK][BN];

    const int tid = threadIdx.x;
    const int tx = tid & 15;
    const int ty = tid >> 4;
    const int m0 = blockIdx.y * BM;
    const int n0 = blockIdx.x * BN;

    const int la_r = tid >> 1;        // 0..127
    const int la_k = (tid & 1) * 4;   // 0 or 4

    unsigned long long acc[8][4];
    #pragma unroll
    for (int i = 0; i < 8; i++)
        #pragma unroll
        for (int j = 0; j < 4; j++) acc[i][j] = 0ull;

    float4 av = *(const float4*)(A + (size_t)(m0 + la_r) * K + la_k);
    float4 bv = *(const float4*)(W + (size_t)(n0 + la_r) * K + la_k);

    int buf = 0;
    for (int k0 = 0; k0 < K; k0 += BK) {
        As[buf][la_k + 0][la_r] = av.x; As[buf][la_k + 1][la_r] = av.y;
        As[buf][la_k + 2][la_r] = av.z; As[buf][la_k + 3][la_r] = av.w;
        Bs[buf][la_k + 0][la_r] = bv.x; Bs[buf][la_k + 1][la_r] = bv.y;
        Bs[buf][la_k + 2][la_r] = bv.z; Bs[buf][la_k + 3][la_r] = bv.w;
        __syncthreads();

        if (k0 + BK < K) {
            av = *(const float4*)(A + (size_t)(m0 + la_r) * K + k0 + BK + la_k);
            bv = *(const float4*)(W + (size_t)(n0 + la_r) * K + k0 + BK + la_k);
        }

        #pragma unroll
        for (int kk = 0; kk < BK; kk++) {
            float a[8];
            *(float4*)(a)     = *(const float4*)&As[buf][kk][ty * 4];
            *(float4*)(a + 4) = *(const float4*)&As[buf][kk][ty * 4 + 64];
            ulonglong2 bv0 = *(const ulonglong2*)&Bs[buf][kk][tx * 4];
            ulonglong2 bv1 = *(const ulonglong2*)&Bs[buf][kk][tx * 4 + 64];
            unsigned long long bp[4] = {bv0.x, bv0.y, bv1.x, bv1.y};
            #pragma unroll
            for (int i = 0; i < 8; i++) {
                unsigned long long ap;
                unsigned ai = __float_as_uint(a[i]);
                asm("mov.b64 %0, {%1, %1};" : "=l"(ap) : "r"(ai));
                #pragma unroll
                for (int jp = 0; jp < 4; jp++)
                    fma2(acc[i][jp], ap, bp[jp]);
            }
        }
        buf ^= 1;
    }

    #pragma unroll
    for (int jg = 0; jg < 2; jg++) {
        const int n = n0 + tx * 4 + jg * 64;
        float4 bb = make_float4(0.f, 0.f, 0.f, 0.f);
        if (bias1) {
            float4 t = *(const float4*)(bias1 + n);
            bb.x += t.x; bb.y += t.y; bb.z += t.z; bb.w += t.w;
        }
        if (bias2) {
            float4 t = *(const float4*)(bias2 + n);
            bb.x += t.x; bb.y += t.y; bb.z += t.z; bb.w += t.w;
        }
        #pragma unroll
        for (int i = 0; i < 8; i++) {
            const int ml = (i < 4) ? (ty * 4 + i) : (64 + ty * 4 + i - 4);
            const int m  = m0 + ml;
            unsigned long long p0 = acc[i][jg * 2 + 0];
            unsigned long long p1 = acc[i][jg * 2 + 1];
            float4 v;
            v.x = lo32(p0) + bb.x;
            v.y = hi32(p0) + bb.y;
            v.z = lo32(p1) + bb.z;
            v.w = hi32(p1) + bb.w;
            *(float4*)(C + (size_t)m * N + n) = v;
        }
    }
}

// ---------------------------------------------------------------------------
// Persistent RNN layer: r[:,t,:] = tanh(xp[:,t,:] + r[:,t-1,:] @ W_hh^T)
//
// Grid: 128 blocks = 4 batch-groups (8 batches) x 32 col-groups (32 cols).
// Block: 512 threads = 16 warps; warp <-> k-chunk (64 k), lane <-> col.
// Per step: each warp stages ONLY ITS OWN 8x64 h slice (warp-local, no block
// sync), computes 8 batch f32x2 accumulators with 8x W-register reuse,
// cross-warp k-reduction via psm (1 syncthreads), then activation + store +
// per-group barrier (1 syncthreads). xp prefetched under compute.
// ---------------------------------------------------------------------------
#define WPAD 1028                      // 1028 % 32 == 4 -> conflict-free LDS.128
#define RNN_BLOCKS 128
#define RNN_SMEM_FLOATS (32 * WPAD + 16 * 512 + 16 * 256)

__global__ __launch_bounds__(512) void rnn_layer_kernel(
    int rsel, const float* __restrict__ W)
{
    float* r = (rsel == SEL_R1) ? g_r1 : g_r2;

    extern __shared__ float sm[];
    float* Wsm = sm;                       // 32 x WPAD
    float* hsm = sm + 32 * WPAD;           // 16 warps x (8 batches x 64 k)
    float* psm = sm + 32 * WPAD + 16 * 512; // 16 x 8 x 32 partials

    const int tid  = threadIdx.x;
    const int warp = tid >> 5;             // k-chunk 0..15
    const int lane = tid & 31;             // col within group
    const int bg = blockIdx.x >> 5;        // 0..3
    const int cg = blockIdx.x & 31;        // 0..31
    const int b0 = bg * 8;
    const int c0 = cg * 32;
    const int kbase = warp * 64;

    // stage W rows c0..c0+31 (full K) once: 8192 float4, 16 per thread
    #pragma unroll
    for (int i = tid; i < 8192; i += 512) {
        const int rr = i >> 8;
        const int q  = (i & 255) << 2;
        *(float4*)&Wsm[rr * WPAD + q] =
            *(const float4*)(W + (size_t)(c0 + rr) * HH + q);
    }
    __syncthreads();

    const ulonglong2* wp = (const ulonglong2*)&Wsm[lane * WPAD + kbase];
    float* hw = &hsm[warp * 512];
    // staging decomposition: i = j*32+lane -> (row, quad)
    const int st_r0 = lane >> 4;           // via i>>4 pattern below
    volatile unsigned* cnt = &g_cnt4[bg * 32];

    // xp pointer for this thread's activation element (warps 0-7 only)
    const float* xp_ptr = g_xp + ((size_t)(b0 + warp) * LL) * HH + (c0 + lane);
    float*       r_ptr  = r    + ((size_t)(b0 + warp) * LL) * HH + (c0 + lane);

    for (int t = 0; t < LL; t++) {
        float xq = 0.0f;
        if (t > 0) {
            // warp-local h staging: 4 float4 per thread (own k-chunk, 8 rows)
            const float* hsrc = r + (size_t)(t - 1) * HH + kbase;
            #pragma unroll
            for (int j = 0; j < 4; j++) {
                const int i  = j * 32 + lane;
                const int rr = i >> 4;            // 0..7
                const int qq = (i & 15) << 2;     // 0..60
                *(float4*)&hw[rr * 64 + qq] =
                    *(const float4*)(hsrc + (size_t)(b0 + rr) * LL * HH + qq);
            }
            __syncwarp();

            // prefetch xp under the FMA block
            if (warp < 8) xq = __ldg(xp_ptr + (size_t)t * HH);

            unsigned long long acc[8];
            #pragma unroll
            for (int b = 0; b < 8; b++) acc[b] = 0ull;

            #pragma unroll 4
            for (int q = 0; q < 16; q++) {
                const ulonglong2 wv = wp[q];
                #pragma unroll
                for (int b = 0; b < 8; b++) {
                    const ulonglong2 hv = *(const ulonglong2*)&hw[b * 64 + q * 4];
                    fma2(acc[b], wv.x, hv.x);
                    fma2(acc[b], wv.y, hv.y);
                }
            }

            #pragma unroll
            for (int b = 0; b < 8; b++)
                psm[warp * 256 + b * 32 + lane] = lo32(acc[b]) + hi32(acc[b]);
            __syncthreads();
        } else {
            if (warp < 8) xq = __ldg(xp_ptr);
        }

        // reduction + activation: warp = batch (0..7), lane = col
        if (warp < 8) {
            float dot = 0.0f;
            if (t > 0) {
                #pragma unroll
                for (int w = 0; w < 16; w++)
                    dot += psm[w * 256 + warp * 32 + lane];
            }
            r_ptr[(size_t)t * HH] = fast_tanh(xq + dot);
        }

        // ---- per-batch-group barrier (release h_t to the 32 peer blocks) ----
        if (t < LL - 1) {
            __threadfence();
            __syncthreads();
            if (tid == 0) {
                atomicAdd((unsigned*)cnt, 1u);
                const unsigned target = 32u * (unsigned)(t + 1);
                while (*cnt < target) { }
            }
            __syncthreads();
        }
    }
}

// reset barrier counters (before each rnn layer -> deterministic replays)
__global__ void rnn_init_kernel()
{
    if (threadIdx.x < 4) g_cnt4[threadIdx.x * 32] = 0u;
}

// ---------------------------------------------------------------------------
// Launch: 8 graph nodes
// ---------------------------------------------------------------------------
extern "C" void kernel_launch(void* const* d_in, const int* in_sizes, int n_in,
                              void* d_out, int out_size)
{
    const float* x     = (const float*)d_in[0];
    const float* W_ih1 = (const float*)d_in[1];
    const float* W_hh1 = (const float*)d_in[2];
    const float* b_ih1 = (const float*)d_in[3];
    const float* b_hh1 = (const float*)d_in[4];
    const float* W_ih2 = (const float*)d_in[5];
    const float* W_hh2 = (const float*)d_in[6];
    const float* b_ih2 = (const float*)d_in[7];
    const float* b_hh2 = (const float*)d_in[8];
    const float* W1    = (const float*)d_in[9];
    const float* b1    = (const float*)d_in[10];
    const float* W2    = (const float*)d_in[11];
    const float* b2    = (const float*)d_in[12];
    float* out = (float*)d_out;

    static int smem_set = 0;
    if (!smem_set) {
        cudaFuncSetAttribute(rnn_layer_kernel,
                             cudaFuncAttributeMaxDynamicSharedMemorySize,
                             RNN_SMEM_FLOATS * sizeof(float));
        smem_set = 1;
    }
    const size_t rnn_smem = RNN_SMEM_FLOATS * sizeof(float);

    const dim3 gBig(HH / BN, BL / BM);   // (8, 128)
    const dim3 gOut(OO / BN, BL / BM);   // (1, 128)

    // xp = x @ W_ih1^T + b_ih1 + b_hh1
    sgemm_bias<<<gBig, 256>>>(x, SEL_EXT, W_ih1, nullptr, SEL_XP,
                              b_ih1, b_hh1, BL, HH, EE);
    // layer 1 recurrence (persistent)
    rnn_init_kernel<<<1, 32>>>();
    rnn_layer_kernel<<<RNN_BLOCKS, 512, rnn_smem>>>(SEL_R1, W_hh1);

    // xp = r1 @ W_ih2^T + b_ih2 + b_hh2
    sgemm_bias<<<gBig, 256>>>(nullptr, SEL_R1, W_ih2, nullptr, SEL_XP,
                              b_ih2, b_hh2, BL, HH, HH);
    // layer 2 recurrence (persistent)
    rnn_init_kernel<<<1, 32>>>();
    rnn_layer_kernel<<<RNN_BLOCKS, 512, rnn_smem>>>(SEL_R2, W_hh2);

    // y = r1 @ W1^T + b1 ; z = r2 @ W2^T + b2
    sgemm_bias<<<gOut, 256>>>(nullptr, SEL_R1, W1, out, SEL_EXT,
                              b1, nullptr, BL, OO, HH);
    sgemm_bias<<<gOut, 256>>>(nullptr, SEL_R2, W2, out + (size_t)BL * OO, SEL_EXT,
                              b2, nullptr, BL, OO, HH);
}